// round 3
// baseline (speedup 1.0000x reference)
#include <cuda_runtime.h>

#define HID 128
#define HEADS 4
#define DIM 32
#define NT 8
#define ETY 8

#define N_SRC_MAX 200000
#define N_CTR_MAX 100000
#define N_EDGE_MAX 800000
#define OSRC_LEN (N_SRC_MAX + 1024)
#define ODST_LEN (N_CTR_MAX + 1024)

typedef unsigned long long u64;

__device__ __forceinline__ u64 pk2(float x, float y) {
    u64 r; asm("mov.b64 %0,{%1,%2};" : "=l"(r) : "f"(x), "f"(y)); return r;
}
__device__ __forceinline__ void up2(float& x, float& y, u64 v) {
    asm("mov.b64 {%0,%1},%2;" : "=f"(x), "=f"(y) : "l"(v));
}
__device__ __forceinline__ u64 f2fma(u64 a, u64 b, u64 c) {
    u64 d; asm("fma.rn.f32x2 %0,%1,%2,%3;" : "=l"(d) : "l"(a), "l"(b), "l"(c)); return d;
}

// ---------------- scratch (device globals; no runtime allocation) ----------------
__device__ float g_k[(size_t)N_SRC_MAX * HID];
__device__ float g_v[(size_t)N_SRC_MAX * HID];
__device__ float g_q[(size_t)N_CTR_MAX * HID];
__device__ float g_a[(size_t)N_EDGE_MAX * HEADS];       // scores, then alpha in-place
__device__ float g_mw[(size_t)N_EDGE_MAX * HID];        // alpha-scaled messages (410MB)
__device__ int   g_dstid[N_EDGE_MAX];
__device__ int   g_eord[N_EDGE_MAX];
__device__ int   g_osrc[OSRC_LEN];
__device__ int   g_odst[ODST_LEN];
__device__ int   g_cnt[16];
__device__ int   g_pos[16];
__device__ int   g_ecnt[8];
__device__ int   g_epos[8];

// ---------------- prep: counting sorts ----------------
__global__ void init_kernel() {
    int i = blockIdx.x * blockDim.x + threadIdx.x;
    int stride = gridDim.x * blockDim.x;
    if (i < 16) { g_cnt[i] = 0; g_pos[i] = 0; }
    if (i < 8)  { g_ecnt[i] = 0; g_epos[i] = 0; }
    for (int j = i; j < OSRC_LEN; j += stride) g_osrc[j] = -1;
    for (int j = i; j < ODST_LEN; j += stride) g_odst[j] = -1;
}

__global__ void hist_kernel(const int* __restrict__ ntype, int num_src, int num_center) {
    __shared__ int sc[16];
    if (threadIdx.x < 16) sc[threadIdx.x] = 0;
    __syncthreads();
    int n = blockIdx.x * blockDim.x + threadIdx.x;
    if (n < num_src) {
        int t = ntype[n];
        atomicAdd(&sc[t], 1);
        if (n < num_center) atomicAdd(&sc[8 + t], 1);
    }
    __syncthreads();
    if (threadIdx.x < 16 && sc[threadIdx.x]) atomicAdd(&g_cnt[threadIdx.x], sc[threadIdx.x]);
}

__global__ void ehist_kernel(const int* __restrict__ etype, int E) {
    __shared__ int sc[8];
    if (threadIdx.x < 8) sc[threadIdx.x] = 0;
    __syncthreads();
    int e = blockIdx.x * blockDim.x + threadIdx.x;
    if (e < E) atomicAdd(&sc[etype[e]], 1);
    __syncthreads();
    if (threadIdx.x < 8 && sc[threadIdx.x]) atomicAdd(&g_ecnt[threadIdx.x], sc[threadIdx.x]);
}

__global__ void offsets_kernel() {
    if (threadIdx.x == 0 && blockIdx.x == 0) {
        int off = 0;
        for (int t = 0; t < 8; t++) { g_pos[t] = off; off += ((g_cnt[t] + 63) >> 6) << 6; }
        off = 0;
        for (int t = 0; t < 8; t++) { g_pos[8 + t] = off; off += ((g_cnt[8 + t] + 63) >> 6) << 6; }
        off = 0;
        for (int t = 0; t < 8; t++) { g_epos[t] = off; off += g_ecnt[t]; }
    }
}

__global__ void scatter_kernel(const int* __restrict__ ntype, int num_src, int num_center) {
    __shared__ int sc[16];
    __shared__ int sb[16];
    if (threadIdx.x < 16) sc[threadIdx.x] = 0;
    __syncthreads();
    int n = blockIdx.x * blockDim.x + threadIdx.x;
    int t = 0, r1 = -1, r2 = -1;
    if (n < num_src) {
        t = ntype[n];
        r1 = atomicAdd(&sc[t], 1);
        if (n < num_center) r2 = atomicAdd(&sc[8 + t], 1);
    }
    __syncthreads();
    if (threadIdx.x < 16)
        sb[threadIdx.x] = sc[threadIdx.x] ? atomicAdd(&g_pos[threadIdx.x], sc[threadIdx.x]) : 0;
    __syncthreads();
    if (r1 >= 0) g_osrc[sb[t] + r1] = n;
    if (r2 >= 0) g_odst[sb[8 + t] + r2] = n;
}

__global__ void escatter_kernel(const int* __restrict__ etype, int E) {
    __shared__ int sc[8];
    __shared__ int sb[8];
    if (threadIdx.x < 8) sc[threadIdx.x] = 0;
    __syncthreads();
    int e = blockIdx.x * blockDim.x + threadIdx.x;
    int t = 0, r = -1;
    if (e < E) { t = etype[e]; r = atomicAdd(&sc[t], 1); }
    __syncthreads();
    if (threadIdx.x < 8)
        sb[threadIdx.x] = sc[threadIdx.x] ? atomicAdd(&g_epos[threadIdx.x], sc[threadIdx.x]) : 0;
    __syncthreads();
    if (r >= 0) g_eord[sb[t] + r] = e;
}

// ---------------- typed node projection: dense GEMM on sorted tiles (f32x2) ----------------
__global__ void __launch_bounds__(256, 2) node_gemm_kernel(
    const float* __restrict__ x, const float* __restrict__ W8,
    const int* __restrict__ ntype, int which)
{
    extern __shared__ float sm[];
    float* w_sm = sm;              // 128*128
    float* xT = sm + 128 * 128;    // 128*64 (transposed x tile, m fastest)
    const int* order = (which == 2) ? g_odst : g_osrc;
    float* outp = (which == 0) ? g_k : (which == 1) ? g_v : g_q;

    const int base = blockIdx.x * 64;
    int n0 = order[base];
    if (n0 < 0) return;
    int t = ntype[n0];
    const int tid = threadIdx.x;

    const float4* W4 = (const float4*)(W8 + (size_t)t * 128 * 128);
    float4* w4 = (float4*)w_sm;
#pragma unroll
    for (int i = 0; i < 16; ++i) w4[tid + 256 * i] = W4[tid + 256 * i];

    int m = tid >> 2, q4 = tid & 3;
    int row = order[base + m];
#pragma unroll
    for (int it = 0; it < 8; ++it) {
        int c = q4 * 4 + it * 16;
        float4 xv = make_float4(0.f, 0.f, 0.f, 0.f);
        if (row >= 0) xv = *(const float4*)(x + (size_t)row * 128 + c);
        xT[(c + 0) * 64 + m] = xv.x;
        xT[(c + 1) * 64 + m] = xv.y;
        xT[(c + 2) * 64 + m] = xv.z;
        xT[(c + 3) * 64 + m] = xv.w;
    }
    __syncthreads();

    const int tm = tid >> 5;  // warp id -> 8 m rows (as 4 pairs)
    const int tn = tid & 31;  // lane -> 4 n cols
    u64 acc2[4][4];
#pragma unroll
    for (int i = 0; i < 4; ++i)
#pragma unroll
        for (int j = 0; j < 4; ++j) acc2[i][j] = 0ull;

#pragma unroll 8
    for (int kk = 0; kk < 128; ++kk) {
        const ulonglong2* xp = (const ulonglong2*)(xT + kk * 64 + tm * 8);
        ulonglong2 xa = xp[0];
        ulonglong2 xb = xp[1];
        u64 xs[4] = { xa.x, xa.y, xb.x, xb.y };
        float4 wv = *(const float4*)(w_sm + kk * 128 + tn * 4);
        u64 wd[4] = { pk2(wv.x, wv.x), pk2(wv.y, wv.y), pk2(wv.z, wv.z), pk2(wv.w, wv.w) };
#pragma unroll
        for (int i = 0; i < 4; ++i)
#pragma unroll
            for (int j = 0; j < 4; ++j) acc2[i][j] = f2fma(xs[i], wd[j], acc2[i][j]);
    }

#pragma unroll
    for (int i2 = 0; i2 < 4; ++i2) {
        float r0[4], r1[4];
#pragma unroll
        for (int j = 0; j < 4; ++j) up2(r0[j], r1[j], acc2[i2][j]);
        int m0 = tm * 8 + 2 * i2;
        int ra = order[base + m0], rb = order[base + m0 + 1];
        if (ra >= 0) *(float4*)(outp + (size_t)ra * 128 + tn * 4) = make_float4(r0[0], r0[1], r0[2], r0[3]);
        if (rb >= 0) *(float4*)(outp + (size_t)rb * 128 + tn * 4) = make_float4(r1[0], r1[1], r1[2], r1[3]);
    }
}

// ---------------- dst id fill ----------------
__global__ void fill_dst_kernel(const int* __restrict__ ptr, int C) {
    int c = blockIdx.x * blockDim.x + threadIdx.x;
    if (c >= C) return;
    int e0 = ptr[c], e1 = ptr[c + 1];
    for (int e = e0; e < e1; ++e) g_dstid[e] = c;
}

// ---------------- edge scores: lane-per-edge, etype-sorted ----------------
__global__ void __launch_bounds__(512, 1) scores_kernel(
    const int* __restrict__ idx, const int* __restrict__ etype,
    const float* __restrict__ a_rel, const float* __restrict__ relptr, int E)
{
    extern __shared__ float A_sm[];   // 8*4*32*32 floats = 128KB
    __shared__ float rp[32];
    for (int i = threadIdx.x; i < ETY * HEADS * DIM * DIM; i += blockDim.x) A_sm[i] = a_rel[i];
    if (threadIdx.x < 32) rp[threadIdx.x] = relptr[threadIdx.x];
    __syncthreads();

    const float inv = 0.17677669529663689f; // 1/sqrt(32)
    int stride = gridDim.x * blockDim.x;
    for (int p = blockIdx.x * blockDim.x + threadIdx.x; p < E; p += stride) {
        int e = g_eord[p];
        int s = idx[e];
        int et = etype[e];
        int c = g_dstid[e];
        const float4* kp = (const float4*)(g_k + (size_t)s * HID);
        const ulonglong2* qp = (const ulonglong2*)(g_q + (size_t)c * HID);
        const float* Ab = A_sm + et * (HEADS * DIM * DIM);
        float outv[4];
#pragma unroll 1
        for (int h = 0; h < 4; ++h) {
            u64 kw2[16];
#pragma unroll
            for (int i = 0; i < 16; ++i) kw2[i] = 0ull;
            const ulonglong2* Ar = (const ulonglong2*)(Ab + h * 1024);
#pragma unroll 1
            for (int dg = 0; dg < 8; ++dg) {
                float4 kv = kp[h * 8 + dg];
                float kd[4] = { kv.x, kv.y, kv.z, kv.w };
#pragma unroll
                for (int j = 0; j < 4; ++j) {
                    u64 kd2 = pk2(kd[j], kd[j]);
                    const ulonglong2* A2 = Ar + (size_t)(dg * 4 + j) * 8;
#pragma unroll
                    for (int f = 0; f < 8; ++f) {
                        ulonglong2 aa = A2[f];
                        kw2[2 * f]     = f2fma(kd2, aa.x, kw2[2 * f]);
                        kw2[2 * f + 1] = f2fma(kd2, aa.y, kw2[2 * f + 1]);
                    }
                }
            }
            u64 acc = 0ull;
#pragma unroll
            for (int f = 0; f < 8; ++f) {
                ulonglong2 qq = qp[h * 8 + f];
                acc = f2fma(kw2[2 * f], qq.x, acc);
                acc = f2fma(kw2[2 * f + 1], qq.y, acc);
            }
            float lo, hi; up2(lo, hi, acc);
            outv[h] = (lo + hi) * rp[h * ETY + et] * inv;
        }
        *(float4*)(g_a + (size_t)e * 4) = make_float4(outv[0], outv[1], outv[2], outv[3]);
    }
}

// ---------------- segment softmax: warp per center, alpha written in place ----------------
__global__ void __launch_bounds__(256) softmax_kernel(const int* __restrict__ ptr, int C) {
    int w = (blockIdx.x * blockDim.x + threadIdx.x) >> 5;
    if (w >= C) return;
    const unsigned FULL = 0xffffffffu;
    int lane = threadIdx.x & 31;
    int e0 = ptr[w], e1 = ptr[w + 1];
    if (e1 <= e0) return;
    int deg = e1 - e0;
    int h = lane & 3, el = lane >> 2;
    float mx = __int_as_float(0xff800000);
    for (int i = el; i < deg; i += 8) mx = fmaxf(mx, g_a[(size_t)(e0 + i) * 4 + h]);
    mx = fmaxf(mx, __shfl_xor_sync(FULL, mx, 4));
    mx = fmaxf(mx, __shfl_xor_sync(FULL, mx, 8));
    mx = fmaxf(mx, __shfl_xor_sync(FULL, mx, 16));
    float den = 0.f;
    for (int i = el; i < deg; i += 8) den += __expf(g_a[(size_t)(e0 + i) * 4 + h] - mx);
    den += __shfl_xor_sync(FULL, den, 4);
    den += __shfl_xor_sync(FULL, den, 8);
    den += __shfl_xor_sync(FULL, den, 16);
    float dinv = 1.f / den;
    for (int i = el; i < deg; i += 8) {
        size_t o = (size_t)(e0 + i) * 4 + h;
        g_a[o] = __expf(g_a[o] - mx) * dinv;
    }
}

// ---------------- alpha-scaled messages: lane-per-edge, etype-sorted ----------------
__global__ void __launch_bounds__(512, 1) msg_kernel(
    const int* __restrict__ idx, const int* __restrict__ etype,
    const float* __restrict__ m_rel, int E)
{
    extern __shared__ float M_sm[];   // 128KB
    for (int i = threadIdx.x; i < ETY * HEADS * DIM * DIM; i += blockDim.x) M_sm[i] = m_rel[i];
    __syncthreads();

    int stride = gridDim.x * blockDim.x;
    for (int p = blockIdx.x * blockDim.x + threadIdx.x; p < E; p += stride) {
        int e = g_eord[p];
        int s = idx[e];
        int et = etype[e];
        float4 al = *(const float4*)(g_a + (size_t)e * 4);
        float alh[4] = { al.x, al.y, al.z, al.w };
        const float4* vp = (const float4*)(g_v + (size_t)s * HID);
        float4* op = (float4*)(g_mw + (size_t)e * HID);
        const float* Mb = M_sm + et * (HEADS * DIM * DIM);
#pragma unroll 1
        for (int h = 0; h < 4; ++h) {
            u64 mw2[16];
#pragma unroll
            for (int i = 0; i < 16; ++i) mw2[i] = 0ull;
            const ulonglong2* Mr = (const ulonglong2*)(Mb + h * 1024);
#pragma unroll 1
            for (int dg = 0; dg < 8; ++dg) {
                float4 vv = vp[h * 8 + dg];
                float vd[4] = { vv.x, vv.y, vv.z, vv.w };
#pragma unroll
                for (int j = 0; j < 4; ++j) {
                    u64 vd2 = pk2(vd[j], vd[j]);
                    const ulonglong2* M2 = Mr + (size_t)(dg * 4 + j) * 8;
#pragma unroll
                    for (int f = 0; f < 8; ++f) {
                        ulonglong2 mm = M2[f];
                        mw2[2 * f]     = f2fma(vd2, mm.x, mw2[2 * f]);
                        mw2[2 * f + 1] = f2fma(vd2, mm.y, mw2[2 * f + 1]);
                    }
                }
            }
            float ah = alh[h];
#pragma unroll
            for (int f = 0; f < 8; ++f) {
                float x0, x1, x2, x3;
                up2(x0, x1, mw2[2 * f]);
                up2(x2, x3, mw2[2 * f + 1]);
                op[h * 8 + f] = make_float4(x0 * ah, x1 * ah, x2 * ah, x3 * ah);
            }
        }
    }
}

// ---------------- final segment sum: warp per center, fully coalesced ----------------
__global__ void __launch_bounds__(256) agg_kernel(const int* __restrict__ ptr,
                                                  float* __restrict__ out, int C) {
    int w = (blockIdx.x * blockDim.x + threadIdx.x) >> 5;
    if (w >= C) return;
    int lane = threadIdx.x & 31;
    int e0 = ptr[w], e1 = ptr[w + 1];
    float4 o = make_float4(0.f, 0.f, 0.f, 0.f);
    for (int e = e0; e < e1; ++e) {
        float4 m4 = *(const float4*)(g_mw + (size_t)e * HID + lane * 4);
        o.x += m4.x; o.y += m4.y; o.z += m4.z; o.w += m4.w;
    }
    *(float4*)(out + (size_t)w * HID + lane * 4) = o;
}

// ---------------- host launcher ----------------
extern "C" void kernel_launch(void* const* d_in, const int* in_sizes, int n_in,
                              void* d_out, int out_size)
{
    (void)out_size;
    const float* x     = (const float*)d_in[0];
    const int*   ptr   = (const int*)d_in[1];
    const int*   idx   = (const int*)d_in[2];
    const int*   ntype = (const int*)d_in[3];
    const int*   etype = (const int*)d_in[4];
    int wb = n_in - 6;
    const float* k_lin = (const float*)d_in[wb + 0];
    const float* q_lin = (const float*)d_in[wb + 1];
    const float* v_lin = (const float*)d_in[wb + 2];
    const float* a_rel = (const float*)d_in[wb + 3];
    const float* m_rel = (const float*)d_in[wb + 4];
    const float* relp  = (const float*)d_in[wb + 5];

    int num_src    = in_sizes[3];
    int num_edge   = in_sizes[2];
    int num_center = in_sizes[1] - 1;
    float* out = (float*)d_out;

    cudaFuncSetAttribute(node_gemm_kernel, cudaFuncAttributeMaxDynamicSharedMemorySize, 98304);
    cudaFuncSetAttribute(scores_kernel,    cudaFuncAttributeMaxDynamicSharedMemorySize, 131072);
    cudaFuncSetAttribute(msg_kernel,       cudaFuncAttributeMaxDynamicSharedMemorySize, 131072);

    init_kernel<<<600, 512>>>();
    hist_kernel<<<(num_src + 255) / 256, 256>>>(ntype, num_src, num_center);
    ehist_kernel<<<(num_edge + 255) / 256, 256>>>(etype, num_edge);
    offsets_kernel<<<1, 32>>>();
    scatter_kernel<<<(num_src + 255) / 256, 256>>>(ntype, num_src, num_center);
    escatter_kernel<<<(num_edge + 255) / 256, 256>>>(etype, num_edge);

    int tiles_src = (num_src + 63) / 64 + 8;
    int tiles_dst = (num_center + 63) / 64 + 8;
    node_gemm_kernel<<<tiles_src, 256, 98304>>>(x, k_lin, ntype, 0);
    node_gemm_kernel<<<tiles_src, 256, 98304>>>(x, v_lin, ntype, 1);
    node_gemm_kernel<<<tiles_dst, 256, 98304>>>(x, q_lin, ntype, 2);

    fill_dst_kernel<<<(num_center + 255) / 256, 256>>>(ptr, num_center);

    scores_kernel<<<148, 512, 131072>>>(idx, etype, a_rel, relp, num_edge);
    softmax_kernel<<<(num_center + 7) / 8, 256>>>(ptr, num_center);
    msg_kernel<<<148, 512, 131072>>>(idx, etype, m_rel, num_edge);
    agg_kernel<<<(num_center + 7) / 8, 256>>>(ptr, out, num_center);
}

// round 4
// speedup vs baseline: 1.0188x; 1.0188x over previous
#include <cuda_runtime.h>

#define HID 128
#define HEADS 4
#define DIM 32
#define NT 8
#define ETY 8

#define N_SRC_MAX 200000
#define N_CTR_MAX 100000
#define N_EDGE_MAX 800000
#define OSRC_LEN (N_SRC_MAX + 1024)
#define ODST_LEN (N_CTR_MAX + 1024)

typedef unsigned long long u64;

__device__ __forceinline__ u64 pk2(float x, float y) {
    u64 r; asm("mov.b64 %0,{%1,%2};" : "=l"(r) : "f"(x), "f"(y)); return r;
}
__device__ __forceinline__ void up2(float& x, float& y, u64 v) {
    asm("mov.b64 {%0,%1},%2;" : "=f"(x), "=f"(y) : "l"(v));
}
__device__ __forceinline__ u64 f2fma(u64 a, u64 b, u64 c) {
    u64 d; asm("fma.rn.f32x2 %0,%1,%2,%3;" : "=l"(d) : "l"(a), "l"(b), "l"(c)); return d;
}

// ---------------- scratch (device globals; no runtime allocation) ----------------
__device__ float g_k[(size_t)N_SRC_MAX * HID];
__device__ float g_v[(size_t)N_SRC_MAX * HID];
__device__ float g_q[(size_t)N_CTR_MAX * HID];
__device__ float g_a[(size_t)N_EDGE_MAX * HEADS];   // edge scores
__device__ int   g_dstid[N_EDGE_MAX];
__device__ int   g_eord[N_EDGE_MAX];
__device__ int   g_osrc[OSRC_LEN];
__device__ int   g_odst[ODST_LEN];
__device__ int   g_cnt[16];
__device__ int   g_pos[16];
__device__ int   g_ecnt[8];
__device__ int   g_epos[8];

// ---------------- prep: counting sorts ----------------
__global__ void init_kernel() {
    int i = blockIdx.x * blockDim.x + threadIdx.x;
    int stride = gridDim.x * blockDim.x;
    if (i < 16) { g_cnt[i] = 0; g_pos[i] = 0; }
    if (i < 8)  { g_ecnt[i] = 0; g_epos[i] = 0; }
    for (int j = i; j < OSRC_LEN; j += stride) g_osrc[j] = -1;
    for (int j = i; j < ODST_LEN; j += stride) g_odst[j] = -1;
}

__global__ void hist_kernel(const int* __restrict__ ntype, int num_src, int num_center) {
    __shared__ int sc[16];
    if (threadIdx.x < 16) sc[threadIdx.x] = 0;
    __syncthreads();
    int n = blockIdx.x * blockDim.x + threadIdx.x;
    if (n < num_src) {
        int t = ntype[n];
        atomicAdd(&sc[t], 1);
        if (n < num_center) atomicAdd(&sc[8 + t], 1);
    }
    __syncthreads();
    if (threadIdx.x < 16 && sc[threadIdx.x]) atomicAdd(&g_cnt[threadIdx.x], sc[threadIdx.x]);
}

__global__ void ehist_kernel(const int* __restrict__ etype, int E) {
    __shared__ int sc[8];
    if (threadIdx.x < 8) sc[threadIdx.x] = 0;
    __syncthreads();
    int e = blockIdx.x * blockDim.x + threadIdx.x;
    if (e < E) atomicAdd(&sc[etype[e]], 1);
    __syncthreads();
    if (threadIdx.x < 8 && sc[threadIdx.x]) atomicAdd(&g_ecnt[threadIdx.x], sc[threadIdx.x]);
}

__global__ void offsets_kernel() {
    if (threadIdx.x == 0 && blockIdx.x == 0) {
        int off = 0;
        for (int t = 0; t < 8; t++) { g_pos[t] = off; off += ((g_cnt[t] + 63) >> 6) << 6; }
        off = 0;
        for (int t = 0; t < 8; t++) { g_pos[8 + t] = off; off += ((g_cnt[8 + t] + 63) >> 6) << 6; }
        off = 0;
        for (int t = 0; t < 8; t++) { g_epos[t] = off; off += g_ecnt[t]; }
    }
}

__global__ void scatter_kernel(const int* __restrict__ ntype, int num_src, int num_center) {
    __shared__ int sc[16];
    __shared__ int sb[16];
    if (threadIdx.x < 16) sc[threadIdx.x] = 0;
    __syncthreads();
    int n = blockIdx.x * blockDim.x + threadIdx.x;
    int t = 0, r1 = -1, r2 = -1;
    if (n < num_src) {
        t = ntype[n];
        r1 = atomicAdd(&sc[t], 1);
        if (n < num_center) r2 = atomicAdd(&sc[8 + t], 1);
    }
    __syncthreads();
    if (threadIdx.x < 16)
        sb[threadIdx.x] = sc[threadIdx.x] ? atomicAdd(&g_pos[threadIdx.x], sc[threadIdx.x]) : 0;
    __syncthreads();
    if (r1 >= 0) g_osrc[sb[t] + r1] = n;
    if (r2 >= 0) g_odst[sb[8 + t] + r2] = n;
}

__global__ void escatter_kernel(const int* __restrict__ etype, int E) {
    __shared__ int sc[8];
    __shared__ int sb[8];
    if (threadIdx.x < 8) sc[threadIdx.x] = 0;
    __syncthreads();
    int e = blockIdx.x * blockDim.x + threadIdx.x;
    int t = 0, r = -1;
    if (e < E) { t = etype[e]; r = atomicAdd(&sc[t], 1); }
    __syncthreads();
    if (threadIdx.x < 8)
        sb[threadIdx.x] = sc[threadIdx.x] ? atomicAdd(&g_epos[threadIdx.x], sc[threadIdx.x]) : 0;
    __syncthreads();
    if (r >= 0) g_eord[sb[t] + r] = e;
}

// ---------------- typed node projection: dense GEMM on sorted tiles (f32x2) ----------------
__global__ void __launch_bounds__(256, 2) node_gemm_kernel(
    const float* __restrict__ x, const float* __restrict__ W8,
    const int* __restrict__ ntype, int which)
{
    extern __shared__ float sm[];
    float* w_sm = sm;              // 128*128
    float* xT = sm + 128 * 128;    // 128*64 (transposed x tile, m fastest)
    const int* order = (which == 2) ? g_odst : g_osrc;
    float* outp = (which == 0) ? g_k : (which == 1) ? g_v : g_q;

    const int base = blockIdx.x * 64;
    int n0 = order[base];
    if (n0 < 0) return;
    int t = ntype[n0];
    const int tid = threadIdx.x;

    const float4* W4 = (const float4*)(W8 + (size_t)t * 128 * 128);
    float4* w4 = (float4*)w_sm;
#pragma unroll
    for (int i = 0; i < 16; ++i) w4[tid + 256 * i] = W4[tid + 256 * i];

    int m = tid >> 2, q4 = tid & 3;
    int row = order[base + m];
#pragma unroll
    for (int it = 0; it < 8; ++it) {
        int c = q4 * 4 + it * 16;
        float4 xv = make_float4(0.f, 0.f, 0.f, 0.f);
        if (row >= 0) xv = *(const float4*)(x + (size_t)row * 128 + c);
        xT[(c + 0) * 64 + m] = xv.x;
        xT[(c + 1) * 64 + m] = xv.y;
        xT[(c + 2) * 64 + m] = xv.z;
        xT[(c + 3) * 64 + m] = xv.w;
    }
    __syncthreads();

    const int tm = tid >> 5;  // warp id -> 8 m rows (as 4 pairs)
    const int tn = tid & 31;  // lane -> 4 n cols
    u64 acc2[4][4];
#pragma unroll
    for (int i = 0; i < 4; ++i)
#pragma unroll
        for (int j = 0; j < 4; ++j) acc2[i][j] = 0ull;

#pragma unroll 8
    for (int kk = 0; kk < 128; ++kk) {
        const ulonglong2* xp = (const ulonglong2*)(xT + kk * 64 + tm * 8);
        ulonglong2 xa = xp[0];
        ulonglong2 xb = xp[1];
        u64 xs[4] = { xa.x, xa.y, xb.x, xb.y };
        float4 wv = *(const float4*)(w_sm + kk * 128 + tn * 4);
        u64 wd[4] = { pk2(wv.x, wv.x), pk2(wv.y, wv.y), pk2(wv.z, wv.z), pk2(wv.w, wv.w) };
#pragma unroll
        for (int i = 0; i < 4; ++i)
#pragma unroll
            for (int j = 0; j < 4; ++j) acc2[i][j] = f2fma(xs[i], wd[j], acc2[i][j]);
    }

#pragma unroll
    for (int i2 = 0; i2 < 4; ++i2) {
        float r0[4], r1[4];
#pragma unroll
        for (int j = 0; j < 4; ++j) up2(r0[j], r1[j], acc2[i2][j]);
        int m0 = tm * 8 + 2 * i2;
        int ra = order[base + m0], rb = order[base + m0 + 1];
        if (ra >= 0) *(float4*)(outp + (size_t)ra * 128 + tn * 4) = make_float4(r0[0], r0[1], r0[2], r0[3]);
        if (rb >= 0) *(float4*)(outp + (size_t)rb * 128 + tn * 4) = make_float4(r1[0], r1[1], r1[2], r1[3]);
    }
}

// ---------------- dst id fill ----------------
__global__ void fill_dst_kernel(const int* __restrict__ ptr, int C) {
    int c = blockIdx.x * blockDim.x + threadIdx.x;
    if (c >= C) return;
    int e0 = ptr[c], e1 = ptr[c + 1];
    for (int e = e0; e < e1; ++e) g_dstid[e] = c;
}

// ---------------- edge scores: lane-per-edge, etype-sorted ----------------
__global__ void __launch_bounds__(512, 1) scores_kernel(
    const int* __restrict__ idx, const int* __restrict__ etype,
    const float* __restrict__ a_rel, const float* __restrict__ relptr, int E)
{
    extern __shared__ float A_sm[];   // 8*4*32*32 floats = 128KB
    __shared__ float rp[32];
    for (int i = threadIdx.x; i < ETY * HEADS * DIM * DIM; i += blockDim.x) A_sm[i] = a_rel[i];
    if (threadIdx.x < 32) rp[threadIdx.x] = relptr[threadIdx.x];
    __syncthreads();

    const float inv = 0.17677669529663689f; // 1/sqrt(32)
    int stride = gridDim.x * blockDim.x;
    for (int p = blockIdx.x * blockDim.x + threadIdx.x; p < E; p += stride) {
        int e = g_eord[p];
        int s = idx[e];
        int et = etype[e];
        int c = g_dstid[e];
        const float4* kp = (const float4*)(g_k + (size_t)s * HID);
        const ulonglong2* qp = (const ulonglong2*)(g_q + (size_t)c * HID);
        const float* Ab = A_sm + et * (HEADS * DIM * DIM);
        float outv[4];
#pragma unroll 1
        for (int h = 0; h < 4; ++h) {
            u64 kw2[16];
#pragma unroll
            for (int i = 0; i < 16; ++i) kw2[i] = 0ull;
            const ulonglong2* Ar = (const ulonglong2*)(Ab + h * 1024);
#pragma unroll 1
            for (int dg = 0; dg < 8; ++dg) {
                float4 kv = kp[h * 8 + dg];
                float kd[4] = { kv.x, kv.y, kv.z, kv.w };
#pragma unroll
                for (int j = 0; j < 4; ++j) {
                    u64 kd2 = pk2(kd[j], kd[j]);
                    const ulonglong2* A2 = Ar + (size_t)(dg * 4 + j) * 8;
#pragma unroll
                    for (int f = 0; f < 8; ++f) {
                        ulonglong2 aa = A2[f];
                        kw2[2 * f]     = f2fma(kd2, aa.x, kw2[2 * f]);
                        kw2[2 * f + 1] = f2fma(kd2, aa.y, kw2[2 * f + 1]);
                    }
                }
            }
            u64 acc = 0ull;
#pragma unroll
            for (int f = 0; f < 8; ++f) {
                ulonglong2 qq = qp[h * 8 + f];
                acc = f2fma(kw2[2 * f], qq.x, acc);
                acc = f2fma(kw2[2 * f + 1], qq.y, acc);
            }
            float lo, hi; up2(lo, hi, acc);
            outv[h] = (lo + hi) * rp[h * ETY + et] * inv;
        }
        *(float4*)(g_a + (size_t)e * 4) = make_float4(outv[0], outv[1], outv[2], outv[3]);
    }
}

// ---------------- fused softmax + type-bucketed aggregation: warp per center ----------------
// out[c] = sum_t (sum_{e in c, type t} alpha[e,h] * v[s,h,:]) @ m_rel[t,h]
// Accumulate per-lane buckets s[t][h] (lane = d), then one 32x32 matvec per present (t,h).
__global__ void __launch_bounds__(1024, 1) fused_agg_kernel(
    const int* __restrict__ ptr, const int* __restrict__ idx,
    const int* __restrict__ etype, const float* __restrict__ m_rel,
    float* __restrict__ out, int C)
{
    extern __shared__ float M_sm[];   // [8][4][32][32] = 128KB
    for (int i = threadIdx.x; i < ETY * HEADS * DIM * DIM; i += blockDim.x) M_sm[i] = m_rel[i];
    __syncthreads();

    const unsigned FULL = 0xffffffffu;
    const int lane = threadIdx.x & 31;
    const int w0 = (blockIdx.x * blockDim.x + threadIdx.x) >> 5;
    const int nw = (gridDim.x * blockDim.x) >> 5;

    for (int c = w0; c < C; c += nw) {
        int e0 = ptr[c], e1 = ptr[c + 1];
        float* ob = out + (size_t)c * HID;
        if (e1 <= e0) {
#pragma unroll
            for (int h = 0; h < 4; ++h) ob[h * 32 + lane] = 0.f;
            continue;
        }
        int deg = e1 - e0;

        // ---- softmax stats (lane layout: h = lane&3, el = lane>>2) ----
        int h4 = lane & 3, el = lane >> 2;
        float mx = __int_as_float(0xff800000);
        for (int i = el; i < deg; i += 8) mx = fmaxf(mx, g_a[(size_t)(e0 + i) * 4 + h4]);
        mx = fmaxf(mx, __shfl_xor_sync(FULL, mx, 4));
        mx = fmaxf(mx, __shfl_xor_sync(FULL, mx, 8));
        mx = fmaxf(mx, __shfl_xor_sync(FULL, mx, 16));
        float den = 0.f;
        for (int i = el; i < deg; i += 8) den += __expf(g_a[(size_t)(e0 + i) * 4 + h4] - mx);
        den += __shfl_xor_sync(FULL, den, 4);
        den += __shfl_xor_sync(FULL, den, 8);
        den += __shfl_xor_sync(FULL, den, 16);
        float dinv = 1.f / den;
        float mxh[4], dih[4];
#pragma unroll
        for (int hh = 0; hh < 4; ++hh) {
            mxh[hh] = __shfl_sync(FULL, mx, hh);
            dih[hh] = __shfl_sync(FULL, dinv, hh);
        }

        // ---- per-type accumulation: sa[t][h], lane = d ----
        float sa[8][4];
#pragma unroll
        for (int t = 0; t < 8; ++t)
#pragma unroll
            for (int h = 0; h < 4; ++h) sa[t][h] = 0.f;
        unsigned tmask = 0u;

        for (int e = e0; e < e1; ++e) {
            int s = idx[e];
            int et = etype[e];
            float4 av = *(const float4*)(g_a + (size_t)e * 4);   // broadcast
            float al0 = __expf(av.x - mxh[0]) * dih[0];
            float al1 = __expf(av.y - mxh[1]) * dih[1];
            float al2 = __expf(av.z - mxh[2]) * dih[2];
            float al3 = __expf(av.w - mxh[3]) * dih[3];
            const float* vb = g_v + (size_t)s * HID;
            float v0 = vb[lane];
            float v1 = vb[32 + lane];
            float v2 = vb[64 + lane];
            float v3 = vb[96 + lane];
            tmask |= (1u << et);
#define ACC_CASE(T) case T: \
            sa[T][0] = fmaf(al0, v0, sa[T][0]); \
            sa[T][1] = fmaf(al1, v1, sa[T][1]); \
            sa[T][2] = fmaf(al2, v2, sa[T][2]); \
            sa[T][3] = fmaf(al3, v3, sa[T][3]); break;
            switch (et) {
                ACC_CASE(0) ACC_CASE(1) ACC_CASE(2) ACC_CASE(3)
                ACC_CASE(4) ACC_CASE(5) ACC_CASE(6) ACC_CASE(7)
            }
#undef ACC_CASE
        }

        // ---- apply M per present (t,h): out[h,d] += sum_d' sa[t][h][d'] * M[t,h,d',d] ----
        float o0 = 0.f, o1 = 0.f, o2 = 0.f, o3 = 0.f;
#pragma unroll 1
        for (int t = 0; t < 8; ++t) {
            if (!((tmask >> t) & 1u)) continue;
            float a0, a1, a2, a3;
            switch (t) {
                case 0: a0 = sa[0][0]; a1 = sa[0][1]; a2 = sa[0][2]; a3 = sa[0][3]; break;
                case 1: a0 = sa[1][0]; a1 = sa[1][1]; a2 = sa[1][2]; a3 = sa[1][3]; break;
                case 2: a0 = sa[2][0]; a1 = sa[2][1]; a2 = sa[2][2]; a3 = sa[2][3]; break;
                case 3: a0 = sa[3][0]; a1 = sa[3][1]; a2 = sa[3][2]; a3 = sa[3][3]; break;
                case 4: a0 = sa[4][0]; a1 = sa[4][1]; a2 = sa[4][2]; a3 = sa[4][3]; break;
                case 5: a0 = sa[5][0]; a1 = sa[5][1]; a2 = sa[5][2]; a3 = sa[5][3]; break;
                case 6: a0 = sa[6][0]; a1 = sa[6][1]; a2 = sa[6][2]; a3 = sa[6][3]; break;
                default: a0 = sa[7][0]; a1 = sa[7][1]; a2 = sa[7][2]; a3 = sa[7][3]; break;
            }
            const float* Mb = M_sm + t * (HEADS * DIM * DIM);   // [h][d'][d]
#pragma unroll
            for (int dp = 0; dp < 32; ++dp) {
                float b0 = __shfl_sync(FULL, a0, dp);
                float b1 = __shfl_sync(FULL, a1, dp);
                float b2 = __shfl_sync(FULL, a2, dp);
                float b3 = __shfl_sync(FULL, a3, dp);
                o0 = fmaf(b0, Mb[(0 * 32 + dp) * 32 + lane], o0);
                o1 = fmaf(b1, Mb[(1 * 32 + dp) * 32 + lane], o1);
                o2 = fmaf(b2, Mb[(2 * 32 + dp) * 32 + lane], o2);
                o3 = fmaf(b3, Mb[(3 * 32 + dp) * 32 + lane], o3);
            }
        }
        ob[lane]      = o0;
        ob[32 + lane] = o1;
        ob[64 + lane] = o2;
        ob[96 + lane] = o3;
    }
}

// ---------------- host launcher ----------------
extern "C" void kernel_launch(void* const* d_in, const int* in_sizes, int n_in,
                              void* d_out, int out_size)
{
    (void)out_size;
    const float* x     = (const float*)d_in[0];
    const int*   ptr   = (const int*)d_in[1];
    const int*   idx   = (const int*)d_in[2];
    const int*   ntype = (const int*)d_in[3];
    const int*   etype = (const int*)d_in[4];
    int wb = n_in - 6;
    const float* k_lin = (const float*)d_in[wb + 0];
    const float* q_lin = (const float*)d_in[wb + 1];
    const float* v_lin = (const float*)d_in[wb + 2];
    const float* a_rel = (const float*)d_in[wb + 3];
    const float* m_rel = (const float*)d_in[wb + 4];
    const float* relp  = (const float*)d_in[wb + 5];

    int num_src    = in_sizes[3];
    int num_edge   = in_sizes[2];
    int num_center = in_sizes[1] - 1;
    float* out = (float*)d_out;

    cudaFuncSetAttribute(node_gemm_kernel, cudaFuncAttributeMaxDynamicSharedMemorySize, 98304);
    cudaFuncSetAttribute(scores_kernel,    cudaFuncAttributeMaxDynamicSharedMemorySize, 131072);
    cudaFuncSetAttribute(fused_agg_kernel, cudaFuncAttributeMaxDynamicSharedMemorySize, 131072);

    init_kernel<<<600, 512>>>();
    hist_kernel<<<(num_src + 255) / 256, 256>>>(ntype, num_src, num_center);
    ehist_kernel<<<(num_edge + 255) / 256, 256>>>(etype, num_edge);
    offsets_kernel<<<1, 32>>>();
    scatter_kernel<<<(num_src + 255) / 256, 256>>>(ntype, num_src, num_center);
    escatter_kernel<<<(num_edge + 255) / 256, 256>>>(etype, num_edge);

    int tiles_src = (num_src + 63) / 64 + 8;
    int tiles_dst = (num_center + 63) / 64 + 8;
    node_gemm_kernel<<<tiles_src, 256, 98304>>>(x, k_lin, ntype, 0);
    node_gemm_kernel<<<tiles_src, 256, 98304>>>(x, v_lin, ntype, 1);
    node_gemm_kernel<<<tiles_dst, 256, 98304>>>(x, q_lin, ntype, 2);

    fill_dst_kernel<<<(num_center + 255) / 256, 256>>>(ptr, num_center);

    scores_kernel<<<148, 512, 131072>>>(idx, etype, a_rel, relp, num_edge);
    fused_agg_kernel<<<148, 1024, 131072>>>(ptr, idx, etype, m_rel, out, num_center);
}